// round 2
// baseline (speedup 1.0000x reference)
#include <cuda_runtime.h>

namespace {
constexpr int CH     = 64;            // output rows per block
constexpr int RITER  = CH + 10;       // rows iterated (with vertical halo)
constexpr int W      = 512;
constexpr int H      = 512;
constexpr int PLANES = 16 * 3;        // N * C
constexpr int CHUNKS = H / CH;        // 8
constexpr int NBLK   = PLANES * CHUNKS;  // 384
constexpr float C1c  = 1e-4f;         // (0.01*1)^2
constexpr float C2c  = 9e-4f;         // (0.03*1)^2
}

// Deterministic per-block partial sums (no float atomics).
__device__ float g_partials[NBLK];

__global__ __launch_bounds__(512, 1)
void ssim_main(const float* __restrict__ X, const float* __restrict__ Y) {
    // Double-buffered padded input rows (zero pad = conv zero padding).
    __shared__ float sxr[2][W + 16];
    __shared__ float syr[2][W + 16];
    __shared__ float wsum[16];

    const int t     = threadIdx.x;        // column 0..511
    const int plane = blockIdx.y;
    const int r0    = blockIdx.x * CH;

    const float* __restrict__ Xp = X + (size_t)plane * W * H;
    const float* __restrict__ Yp = Y + (size_t)plane * W * H;

    // Zero the horizontal pads once (never overwritten afterwards).
    if (t < 5) {
        sxr[0][t] = 0.f; sxr[1][t] = 0.f; syr[0][t] = 0.f; syr[1][t] = 0.f;
        sxr[0][W + 5 + t] = 0.f; sxr[1][W + 5 + t] = 0.f;
        syr[0][W + 5 + t] = 0.f; syr[1][W + 5 + t] = 0.f;
    }

    // Gaussian taps (sigma=1.5, window=11, normalized) as compile-time
    // constants -> FFMA-imm form (rt_SMSP=1).
    const float Gw[6] = {0.00102838f, 0.00759875f, 0.03600077f,
                         0.10936070f, 0.21300554f, 0.26601172f};

    // Register ring buffers: 11 rows of 5 horizontally-blurred quantities.
    float qx[11], qy[11], qxx[11], qyy[11], qxy[11];

    // Prefetch first row (rr = 0 -> image row r0-5).
    float xv, yv;
    {
        const int r = r0 - 5;
        const bool ok = ((unsigned)r < (unsigned)H);
        xv = ok ? Xp[(size_t)r * W + t] : 0.f;
        yv = ok ? Yp[(size_t)r * W + t] : 0.f;
    }

    float acc = 0.f;

    for (int outer = 0; outer < RITER; outer += 11) {
#pragma unroll
        for (int k = 0; k < 11; ++k) {            // ring slot == k (outer % 11 == 0)
            const int rr = outer + k;
            if (rr < RITER) {
                const int buf = rr & 1;
                sxr[buf][t + 5] = xv;
                syr[buf][t + 5] = yv;
                __syncthreads();

                // Prefetch next row right after barrier: DRAM latency
                // overlaps this iteration's compute.
                {
                    const int rn = r0 - 5 + rr + 1;
                    const bool ok = (rr + 1 < RITER) && ((unsigned)rn < (unsigned)H);
                    xv = ok ? Xp[(size_t)rn * W + t] : 0.f;
                    yv = ok ? Yp[(size_t)rn * W + t] : 0.f;
                }

                // ---- Horizontal blur of x, y, x^2, y^2, xy (tap-symmetric) ----
                const float* __restrict__ rxp = sxr[buf];
                const float* __restrict__ ryp = syr[buf];
                const int p = t + 5;

                float hx, hy, hxx, hyy, hxy;
                {
                    const float xc = rxp[p], yc = ryp[p];
                    hx  = Gw[5] * xc;
                    hy  = Gw[5] * yc;
                    hxx = Gw[5] * (xc * xc);
                    hyy = Gw[5] * (yc * yc);
                    hxy = Gw[5] * (xc * yc);
                }
#pragma unroll
                for (int i = 0; i < 5; ++i) {
                    const float xa = rxp[p - 5 + i], xb = rxp[p + 5 - i];
                    const float ya = ryp[p - 5 + i], yb = ryp[p + 5 - i];
                    const float w = Gw[i];
                    hx  = fmaf(w, xa + xb, hx);
                    hy  = fmaf(w, ya + yb, hy);
                    hxx = fmaf(w, fmaf(xb, xb, xa * xa), hxx);
                    hyy = fmaf(w, fmaf(yb, yb, ya * ya), hyy);
                    hxy = fmaf(w, fmaf(xb, yb, xa * ya), hxy);
                }
                qx[k] = hx; qy[k] = hy; qxx[k] = hxx; qyy[k] = hyy; qxy[k] = hxy;

                // ---- Vertical blur + SSIM for output row (rr - 10) ----
                if (rr >= 10) {
                    const int sC = (k + 6) % 11;
                    float vx  = Gw[5] * qx[sC];
                    float vy  = Gw[5] * qy[sC];
                    float vxx = Gw[5] * qxx[sC];
                    float vyy = Gw[5] * qyy[sC];
                    float vxy = Gw[5] * qxy[sC];
#pragma unroll
                    for (int j = 0; j < 5; ++j) {
                        const int sA = (k + j + 1) % 11;    // row offset j
                        const int sB = (k + 11 - j) % 11;   // row offset 10-j
                        const float w = Gw[j];
                        vx  = fmaf(w, qx[sA]  + qx[sB],  vx);
                        vy  = fmaf(w, qy[sA]  + qy[sB],  vy);
                        vxx = fmaf(w, qxx[sA] + qxx[sB], vxx);
                        vyy = fmaf(w, qyy[sA] + qyy[sB], vyy);
                        vxy = fmaf(w, qxy[sA] + qxy[sB], vxy);
                    }
                    const float mxx = vx * vx;
                    const float myy = vy * vy;
                    const float mxy = vx * vy;
                    const float sxx = vxx - mxx;
                    const float syy = vyy - myy;
                    const float sxy = vxy - mxy;
                    const float num = (2.f * mxy + C1c) * (2.f * sxy + C2c);
                    const float den = (mxx + myy + C1c) * (sxx + syy + C2c);
                    acc += __fdividef(num, den + 1e-8f);
                }
            }
        }
    }

    // ---- Deterministic block reduction (shuffle tree + smem) ----
#pragma unroll
    for (int off = 16; off > 0; off >>= 1)
        acc += __shfl_down_sync(0xffffffffu, acc, off);
    const int lane = t & 31, wid = t >> 5;
    if (lane == 0) wsum[wid] = acc;
    __syncthreads();
    if (wid == 0) {
        float v = (lane < 16) ? wsum[lane] : 0.f;
#pragma unroll
        for (int off = 8; off > 0; off >>= 1)
            v += __shfl_down_sync(0xffffffffu, v, off);
        if (lane == 0) g_partials[blockIdx.y * CHUNKS + blockIdx.x] = v;
    }
}

__global__ void ssim_final(float* __restrict__ out) {
    __shared__ float buf[512];
    const int t = threadIdx.x;
    buf[t] = (t < NBLK) ? g_partials[t] : 0.f;
    __syncthreads();
#pragma unroll
    for (int s = 256; s > 0; s >>= 1) {
        if (t < s) buf[t] += buf[t + s];
        __syncthreads();
    }
    if (t == 0) {
        constexpr float invN = 1.0f / (float)((size_t)PLANES * W * H);
        out[0] = 1.0f - buf[0] * invN;
    }
}

extern "C" void kernel_launch(void* const* d_in, const int* in_sizes, int n_in,
                              void* d_out, int out_size) {
    const float* X = (const float*)d_in[0];
    const float* Y = (const float*)d_in[1];
    float* out = (float*)d_out;

    dim3 grid(CHUNKS, PLANES);      // 8 x 48 = 384 blocks
    ssim_main<<<grid, 512>>>(X, Y);
    ssim_final<<<1, 512>>>(out);
}

// round 3
// speedup vs baseline: 1.2488x; 1.2488x over previous
#include <cuda_runtime.h>

namespace {
constexpr int CH     = 64;             // output rows per block
constexpr int RITER  = CH + 10;        // 74 rows iterated (vertical halo)
constexpr int W      = 512;
constexpr int H      = 512;
constexpr int PLANES = 16 * 3;         // 48
constexpr int CHUNKS = H / CH;         // 8
constexpr int NBLK   = PLANES * CHUNKS;   // 384
constexpr int NT     = 256;            // threads; each owns 2 columns
constexpr float C1c  = 1e-4f;
constexpr float C2c  = 9e-4f;
}

__device__ float g_partials[NBLK];

// ---------------- packed f32x2 helpers (sm_103a) ----------------
using u64 = unsigned long long;

__device__ __forceinline__ u64 pk2(float lo, float hi) {
    u64 r; asm("mov.b64 %0, {%1, %2};" : "=l"(r) : "f"(lo), "f"(hi)); return r;
}
__device__ __forceinline__ u64 pkf2(float2 v) { return pk2(v.x, v.y); }
__device__ __forceinline__ void upk2(u64 v, float& lo, float& hi) {
    asm("mov.b64 {%0, %1}, %2;" : "=f"(lo), "=f"(hi) : "l"(v));
}
__device__ __forceinline__ u64 fma2(u64 a, u64 b, u64 c) {
    u64 d; asm("fma.rn.f32x2 %0, %1, %2, %3;" : "=l"(d) : "l"(a), "l"(b), "l"(c)); return d;
}
__device__ __forceinline__ u64 add2(u64 a, u64 b) {
    u64 d; asm("add.rn.f32x2 %0, %1, %2;" : "=l"(d) : "l"(a), "l"(b)); return d;
}
__device__ __forceinline__ u64 mul2(u64 a, u64 b) {
    u64 d; asm("mul.rn.f32x2 %0, %1, %2;" : "=l"(d) : "l"(a), "l"(b)); return d;
}

__global__ __launch_bounds__(NT, 2)
void ssim_main(const float* __restrict__ X, const float* __restrict__ Y) {
    // Horizontal-exchange buffers: 5 quantities, padded rows, double-buffered.
    // Data at index [5 + col]; pads [0..4] and [517..527] stay zero.
    __shared__ float sq[2][5][W + 16];
    __shared__ float wsum[NT / 32];

    const int t     = threadIdx.x;           // column pair index: cols (2t, 2t+1)
    const int plane = blockIdx.y;
    const int r0    = blockIdx.x * CH;

    const float2* __restrict__ X2 =
        reinterpret_cast<const float2*>(X + (size_t)plane * W * H);
    const float2* __restrict__ Y2 =
        reinterpret_cast<const float2*>(Y + (size_t)plane * W * H);

    // Zero pads once (stores below only touch [5 .. 516]).
    if (t < 5) {
#pragma unroll
        for (int q = 0; q < 5; ++q) { sq[0][q][t] = 0.f; sq[1][q][t] = 0.f; }
    }
    if (t < 11) {
#pragma unroll
        for (int q = 0; q < 5; ++q) { sq[0][q][W + 5 + t] = 0.f; sq[1][q][W + 5 + t] = 0.f; }
    }

    // Gaussian taps (sigma=1.5, window=11, normalized), broadcast to lanes.
    const float Gw[6] = {0.00102838f, 0.00759875f, 0.03600077f,
                         0.10936070f, 0.21300554f, 0.26601172f};
    u64 W2[6];
#pragma unroll
    for (int i = 0; i < 6; ++i) W2[i] = pk2(Gw[i], Gw[i]);
    const u64 NEG1 = pk2(-1.f, -1.f);
    const u64 C1_2 = pk2(C1c, C1c);
    const u64 C2_2 = pk2(C2c, C2c);
    const u64 EPS2 = pk2(1e-8f, 1e-8f);

    // Register ring: 11 rows of raw x,y (packed pair of columns).
    u64 xr[11], yr[11];

    // Prefetch first row (rr = 0 -> image row r0-5).
    float2 xv, yv;
    {
        const int r = r0 - 5;
        const bool ok = ((unsigned)r < (unsigned)H);
        xv = ok ? X2[(size_t)r * (W / 2) + t] : make_float2(0.f, 0.f);
        yv = ok ? Y2[(size_t)r * (W / 2) + t] : make_float2(0.f, 0.f);
    }

    float acc = 0.f;

    for (int outer = 0; outer < RITER; outer += 11) {
#pragma unroll
        for (int kk = 0; kk < 11; ++kk) {          // ring slot == kk
            const int rr = outer + kk;
            if (rr < RITER) {
                xr[kk] = pkf2(xv);
                yr[kk] = pkf2(yv);

                // Prefetch next row (overlaps compute below).
                {
                    const int rn = r0 - 5 + rr + 1;
                    const bool ok = (rr + 1 < RITER) && ((unsigned)rn < (unsigned)H);
                    xv = ok ? X2[(size_t)rn * (W / 2) + t] : make_float2(0.f, 0.f);
                    yv = ok ? Y2[(size_t)rn * (W / 2) + t] : make_float2(0.f, 0.f);
                }

                if (rr >= 10) {
                    // ---- Vertical blur (registers only, packed) ----
                    const int sC = (kk + 6) % 11;
                    const u64 xc = xr[sC], yc = yr[sC];
                    u64 vx  = mul2(W2[5], xc);
                    u64 vy  = mul2(W2[5], yc);
                    u64 vxx = mul2(W2[5], mul2(xc, xc));
                    u64 vyy = mul2(W2[5], mul2(yc, yc));
                    u64 vxy = mul2(W2[5], mul2(xc, yc));
#pragma unroll
                    for (int j = 0; j < 5; ++j) {
                        const int sA = (kk + 1 + j) % 11;   // row offset j
                        const int sB = (kk + 11 - j) % 11;  // row offset 10-j
                        const u64 xa = xr[sA], xb = xr[sB];
                        const u64 ya = yr[sA], yb = yr[sB];
                        vx  = fma2(W2[j], add2(xa, xb), vx);
                        vy  = fma2(W2[j], add2(ya, yb), vy);
                        vxx = fma2(W2[j], fma2(xa, xa, mul2(xb, xb)), vxx);
                        vyy = fma2(W2[j], fma2(ya, ya, mul2(yb, yb)), vyy);
                        vxy = fma2(W2[j], fma2(xa, ya, mul2(xb, yb)), vxy);
                    }

                    // ---- Exchange via smem (double-buffered, 1 barrier/row) ----
                    const int buf = rr & 1;
                    {
                        float lo, hi;
                        upk2(vx,  lo, hi); sq[buf][0][5 + 2 * t] = lo; sq[buf][0][6 + 2 * t] = hi;
                        upk2(vy,  lo, hi); sq[buf][1][5 + 2 * t] = lo; sq[buf][1][6 + 2 * t] = hi;
                        upk2(vxx, lo, hi); sq[buf][2][5 + 2 * t] = lo; sq[buf][2][6 + 2 * t] = hi;
                        upk2(vyy, lo, hi); sq[buf][3][5 + 2 * t] = lo; sq[buf][3][6 + 2 * t] = hi;
                        upk2(vxy, lo, hi); sq[buf][4][5 + 2 * t] = lo; sq[buf][4][6 + 2 * t] = hi;
                    }
                    __syncthreads();

                    // ---- Horizontal blur of the 5 quantities (packed) ----
                    u64 h[5];
#pragma unroll
                    for (int q = 0; q < 5; ++q) {
                        const float2* Sp =
                            reinterpret_cast<const float2*>(&sq[buf][q][0]);
                        // scalars [2t .. 2t+11] = cols (2t-5 .. 2t+6), aligned
                        const float2 A0 = Sp[t],     A1 = Sp[t + 1], A2 = Sp[t + 2];
                        const float2 A3 = Sp[t + 3], A4 = Sp[t + 4], A5 = Sp[t + 5];
                        const u64 P0 = pkf2(A0), P2 = pkf2(A1), P4 = pkf2(A2);
                        const u64 P6 = pkf2(A3), P8 = pkf2(A4), P10 = pkf2(A5);
                        const u64 P1 = pk2(A0.y, A1.x), P3 = pk2(A1.y, A2.x);
                        const u64 P5 = pk2(A2.y, A3.x), P7 = pk2(A3.y, A4.x);
                        const u64 P9 = pk2(A4.y, A5.x);
                        u64 hh = mul2(W2[5], P5);
                        hh = fma2(W2[0], add2(P0, P10), hh);
                        hh = fma2(W2[1], add2(P1, P9),  hh);
                        hh = fma2(W2[2], add2(P2, P8),  hh);
                        hh = fma2(W2[3], add2(P3, P7),  hh);
                        hh = fma2(W2[4], add2(P4, P6),  hh);
                        h[q] = hh;
                    }

                    // ---- SSIM (packed) + accumulate ----
                    const u64 hx = h[0], hy = h[1], hxx = h[2], hyy = h[3], hxy = h[4];
                    const u64 mxx = mul2(hx, hx);
                    const u64 myy = mul2(hy, hy);
                    const u64 mxy = mul2(hx, hy);
                    const u64 sxx = fma2(mxx, NEG1, hxx);   // hxx - mxx (exact)
                    const u64 syy = fma2(myy, NEG1, hyy);
                    const u64 sxy = fma2(mxy, NEG1, hxy);
                    const u64 num = mul2(add2(add2(mxy, mxy), C1_2),
                                         add2(add2(sxy, sxy), C2_2));
                    const u64 den = add2(mul2(add2(add2(mxx, myy), C1_2),
                                              add2(add2(sxx, syy), C2_2)), EPS2);
                    float n0, n1, d0, d1;
                    upk2(num, n0, n1);
                    upk2(den, d0, d1);
                    acc += __fdividef(n0, d0);
                    acc += __fdividef(n1, d1);
                }
            }
        }
    }

    // ---- Deterministic block reduction ----
#pragma unroll
    for (int off = 16; off > 0; off >>= 1)
        acc += __shfl_down_sync(0xffffffffu, acc, off);
    const int lane = t & 31, wid = t >> 5;
    if (lane == 0) wsum[wid] = acc;
    __syncthreads();
    if (wid == 0) {
        float v = (lane < NT / 32) ? wsum[lane] : 0.f;
#pragma unroll
        for (int off = 4; off > 0; off >>= 1)
            v += __shfl_down_sync(0xffffffffu, v, off);
        if (lane == 0) g_partials[blockIdx.y * CHUNKS + blockIdx.x] = v;
    }
}

__global__ void ssim_final(float* __restrict__ out) {
    __shared__ float buf[512];
    const int t = threadIdx.x;
    buf[t] = (t < NBLK) ? g_partials[t] : 0.f;
    __syncthreads();
#pragma unroll
    for (int s = 256; s > 0; s >>= 1) {
        if (t < s) buf[t] += buf[t + s];
        __syncthreads();
    }
    if (t == 0) {
        constexpr float invN = 1.0f / (float)((size_t)PLANES * W * H);
        out[0] = 1.0f - buf[0] * invN;
    }
}

extern "C" void kernel_launch(void* const* d_in, const int* in_sizes, int n_in,
                              void* d_out, int out_size) {
    const float* X = (const float*)d_in[0];
    const float* Y = (const float*)d_in[1];
    float* out = (float*)d_out;

    dim3 grid(CHUNKS, PLANES);      // 8 x 48 = 384 blocks, 256 threads each
    ssim_main<<<grid, NT>>>(X, Y);
    ssim_final<<<1, 512>>>(out);
}

// round 4
// speedup vs baseline: 1.4861x; 1.1901x over previous
#include <cuda_runtime.h>

namespace {
constexpr int CH     = 64;             // output rows per block
constexpr int RITER  = CH + 10;        // 74 rows (with vertical halo)
constexpr int W      = 512;
constexpr int H      = 512;
constexpr int PLANES = 16 * 3;         // 48
constexpr int CHUNKS = H / CH;         // 8
constexpr int NBLK   = PLANES * CHUNKS;   // 384
constexpr int NT     = 256;
constexpr int RB     = 528;            // row buffer floats (stride mult of 16B)
constexpr float C1c  = 1e-4f;
constexpr float C2c  = 9e-4f;
}

__device__ float g_partials[NBLK];

// ---------------- packed f32x2 helpers (sm_103a) ----------------
using u64 = unsigned long long;

static __device__ __forceinline__ u64 pk2(float lo, float hi) {
    u64 r; asm("mov.b64 %0, {%1, %2};" : "=l"(r) : "f"(lo), "f"(hi)); return r;
}
static __device__ __forceinline__ u64 pkf2(float2 v) { return pk2(v.x, v.y); }
static __device__ __forceinline__ void upk2(u64 v, float& lo, float& hi) {
    asm("mov.b64 {%0, %1}, %2;" : "=f"(lo), "=f"(hi) : "l"(v));
}
static __device__ __forceinline__ u64 fma2(u64 a, u64 b, u64 c) {
    u64 d; asm("fma.rn.f32x2 %0, %1, %2, %3;" : "=l"(d) : "l"(a), "l"(b), "l"(c)); return d;
}
static __device__ __forceinline__ u64 add2(u64 a, u64 b) {
    u64 d; asm("add.rn.f32x2 %0, %1, %2;" : "=l"(d) : "l"(a), "l"(b)); return d;
}
static __device__ __forceinline__ u64 mul2(u64 a, u64 b) {
    u64 d; asm("mul.rn.f32x2 %0, %1, %2;" : "=l"(d) : "l"(a), "l"(b)); return d;
}
// (a.hi, b.lo) as a packed pair
static __device__ __forceinline__ u64 hilo(u64 a, u64 b) {
    float al, ah, bl, bh; upk2(a, al, ah); upk2(b, bl, bh); return pk2(ah, bl);
}

// Vertical 11-tap blur of x, y, xx, yy, xy from the register ring.
static __device__ __forceinline__ void vert(const u64 xr[11], const u64 yr[11],
                                            int kk, const u64 Wv[6], u64 v[5]) {
    const int sC = (kk + 6) % 11;
    const u64 xc = xr[sC], yc = yr[sC];
    v[0] = mul2(Wv[5], xc);
    v[1] = mul2(Wv[5], yc);
    v[2] = mul2(Wv[5], mul2(xc, xc));
    v[3] = mul2(Wv[5], mul2(yc, yc));
    v[4] = mul2(Wv[5], mul2(xc, yc));
#pragma unroll
    for (int j = 0; j < 5; ++j) {
        const int sA = (kk + 1 + j) % 11;    // row offset j
        const int sB = (kk + 11 - j) % 11;   // row offset 10-j
        const u64 xa = xr[sA], xb = xr[sB];
        const u64 ya = yr[sA], yb = yr[sB];
        v[0] = fma2(Wv[j], add2(xa, xb), v[0]);
        v[1] = fma2(Wv[j], add2(ya, yb), v[1]);
        v[2] = fma2(Wv[j], fma2(xa, xa, mul2(xb, xb)), v[2]);
        v[3] = fma2(Wv[j], fma2(ya, ya, mul2(yb, yb)), v[3]);
        v[4] = fma2(Wv[j], fma2(xa, ya, mul2(xb, yb)), v[4]);
    }
}

static __device__ __forceinline__ float ssim2(const u64 h[5], u64 C1_2, u64 C2_2,
                                              u64 EPS2, u64 NEG1) {
    const u64 mxx = mul2(h[0], h[0]);
    const u64 myy = mul2(h[1], h[1]);
    const u64 mxy = mul2(h[0], h[1]);
    const u64 sxx = fma2(mxx, NEG1, h[2]);
    const u64 syy = fma2(myy, NEG1, h[3]);
    const u64 sxy = fma2(mxy, NEG1, h[4]);
    const u64 num = mul2(add2(add2(mxy, mxy), C1_2), add2(add2(sxy, sxy), C2_2));
    const u64 den = add2(mul2(add2(add2(mxx, myy), C1_2),
                              add2(add2(sxx, syy), C2_2)), EPS2);
    float n0, n1, d0, d1;
    upk2(num, n0, n1);
    upk2(den, d0, d1);
    return __fdividef(n0, d0) + __fdividef(n1, d1);
}

__global__ __launch_bounds__(NT, 2)
void ssim_main(const float* __restrict__ X, const float* __restrict__ Y) {
    // Double-buffered 2-row exchange: [phase-buffer][row-in-phase][quantity][RB]
    // Data for col c at index 6+c; pads [0..5] and [518..527] stay zero.
    __shared__ __align__(16) float sq[2][2][5][RB];
    __shared__ float wsum[NT / 32];

    const int t     = threadIdx.x;          // vertical role: cols (2t, 2t+1)
    const int plane = blockIdx.y;
    const int r0    = blockIdx.x * CH;
    const int hrow  = t >> 7;               // horizontal role: row-in-phase
    const int u     = t & 127;              // horizontal role: cols 4u..4u+3

    const float2* __restrict__ X2 =
        reinterpret_cast<const float2*>(X + (size_t)plane * W * H);
    const float2* __restrict__ Y2 =
        reinterpret_cast<const float2*>(Y + (size_t)plane * W * H);

    // Zero pads once (stores below only touch idx [6 .. 517]).
    if (t < 6) {
#pragma unroll
        for (int pb = 0; pb < 2; ++pb)
#pragma unroll
            for (int r = 0; r < 2; ++r)
#pragma unroll
                for (int q = 0; q < 5; ++q) sq[pb][r][q][t] = 0.f;
    }
    if (t < 10) {
#pragma unroll
        for (int pb = 0; pb < 2; ++pb)
#pragma unroll
            for (int r = 0; r < 2; ++r)
#pragma unroll
                for (int q = 0; q < 5; ++q) sq[pb][r][q][518 + t] = 0.f;
    }

    const float Gw[6] = {0.00102838f, 0.00759875f, 0.03600077f,
                         0.10936070f, 0.21300554f, 0.26601172f};
    u64 Wv[6];
#pragma unroll
    for (int i = 0; i < 6; ++i) Wv[i] = pk2(Gw[i], Gw[i]);
    const u64 NEG1 = pk2(-1.f, -1.f);
    const u64 C1_2 = pk2(C1c, C1c);
    const u64 C2_2 = pk2(C2c, C2c);
    const u64 EPS2 = pk2(1e-8f, 1e-8f);

    // Register ring: 11 rows of raw x,y (packed column pair).
    u64 xr[11], yr[11];

    // Prefetch rows 0,1 (image rows r0-5, r0-4).
    float2 p0x, p0y, p1x, p1y;
    {
        const int ra = r0 - 5, rb = r0 - 4;
        const bool oa = ((unsigned)ra < (unsigned)H);
        const bool ob = ((unsigned)rb < (unsigned)H);
        p0x = oa ? X2[(size_t)ra * (W / 2) + t] : make_float2(0.f, 0.f);
        p0y = oa ? Y2[(size_t)ra * (W / 2) + t] : make_float2(0.f, 0.f);
        p1x = ob ? X2[(size_t)rb * (W / 2) + t] : make_float2(0.f, 0.f);
        p1y = ob ? Y2[(size_t)rb * (W / 2) + t] : make_float2(0.f, 0.f);
    }

    float acc = 0.f;

    for (int outer = 0; outer < RITER; outer += 22) {
#pragma unroll
        for (int ph = 0; ph < 11; ++ph) {
            const int rr = outer + 2 * ph;          // even; processes rows rr, rr+1
            if (rr < RITER) {
                const int k0 = (2 * ph) % 11;       // compile-time after unroll
                const int k1 = (2 * ph + 1) % 11;
                xr[k0] = pkf2(p0x); yr[k0] = pkf2(p0y);
                xr[k1] = pkf2(p1x); yr[k1] = pkf2(p1y);

                // Prefetch rows rr+2, rr+3 (hidden under this phase's compute).
                {
                    const int ra = r0 - 5 + rr + 2, rb = ra + 1;
                    const bool oa = (rr + 2 < RITER) && ((unsigned)ra < (unsigned)H);
                    const bool ob = (rr + 3 < RITER) && ((unsigned)rb < (unsigned)H);
                    p0x = oa ? X2[(size_t)ra * (W / 2) + t] : make_float2(0.f, 0.f);
                    p0y = oa ? Y2[(size_t)ra * (W / 2) + t] : make_float2(0.f, 0.f);
                    p1x = ob ? X2[(size_t)rb * (W / 2) + t] : make_float2(0.f, 0.f);
                    p1y = ob ? Y2[(size_t)rb * (W / 2) + t] : make_float2(0.f, 0.f);
                }

                if (rr >= 10) {
                    const int pb = (rr >> 1) & 1;   // phase buffer

                    // ---- Vertical blur for output rows rr, rr+1 ----
                    u64 v0[5], v1[5];
                    vert(xr, yr, k0, Wv, v0);
                    vert(xr, yr, k1, Wv, v1);

                    // ---- Exchange: aligned STS.64 (idx 6+2t is even) ----
#pragma unroll
                    for (int q = 0; q < 5; ++q) {
                        *reinterpret_cast<u64*>(&sq[pb][0][q][6 + 2 * t]) = v0[q];
                        *reinterpret_cast<u64*>(&sq[pb][1][q][6 + 2 * t]) = v1[q];
                    }
                    __syncthreads();     // one barrier per 2-row phase

                    // ---- Horizontal: 4 cols of row (rr + hrow) per thread ----
                    u64 hA[5], hB[5];    // output pairs m=0 (cols 4u,4u+1), m=1
#pragma unroll
                    for (int q = 0; q < 5; ++q) {
                        const float4* P =
                            reinterpret_cast<const float4*>(&sq[pb][hrow][q][4 * u]);
                        const float4 a = P[0], b = P[1], c = P[2], d = P[3];
                        // U_j = cols (4u-6+2j, 4u-5+2j), j=0..7
                        const u64 U0 = pk2(a.x, a.y), U1 = pk2(a.z, a.w);
                        const u64 U2 = pk2(b.x, b.y), U3 = pk2(b.z, b.w);
                        const u64 U4 = pk2(c.x, c.y), U5 = pk2(c.z, c.w);
                        const u64 U6 = pk2(d.x, d.y), U7 = pk2(d.z, d.w);
                        // adjacent / stride-3 / stride-5 sums for odd taps
                        const u64 A2 = add2(U2, U3), A3 = add2(U3, U4), A4 = add2(U4, U5);
                        const u64 B1 = add2(U1, U4), B2 = add2(U2, U5), B3 = add2(U3, U6);
                        const u64 Cg0 = add2(U0, U5), Cg1 = add2(U1, U6), Cg2 = add2(U2, U7);
                        // m = 0
                        u64 h = mul2(Wv[5], U3);
                        h = fma2(Wv[3], add2(U2, U4), h);
                        h = fma2(Wv[1], add2(U1, U5), h);
                        h = fma2(Wv[4], hilo(A2, A3), h);
                        h = fma2(Wv[2], hilo(B1, B2), h);
                        h = fma2(Wv[0], hilo(Cg0, Cg1), h);
                        hA[q] = h;
                        // m = 1
                        u64 g = mul2(Wv[5], U4);
                        g = fma2(Wv[3], add2(U3, U5), g);
                        g = fma2(Wv[1], add2(U2, U6), g);
                        g = fma2(Wv[4], hilo(A3, A4), g);
                        g = fma2(Wv[2], hilo(B2, B3), g);
                        g = fma2(Wv[0], hilo(Cg1, Cg2), g);
                        hB[q] = g;
                    }

                    acc += ssim2(hA, C1_2, C2_2, EPS2, NEG1);
                    acc += ssim2(hB, C1_2, C2_2, EPS2, NEG1);
                    // No second barrier: next phase writes the other buffer;
                    // its barrier orders these reads before the re-write 2
                    // phases later.
                }
            }
        }
    }

    // ---- Deterministic block reduction ----
#pragma unroll
    for (int off = 16; off > 0; off >>= 1)
        acc += __shfl_down_sync(0xffffffffu, acc, off);
    const int lane = t & 31, wid = t >> 5;
    if (lane == 0) wsum[wid] = acc;
    __syncthreads();
    if (wid == 0) {
        float v = (lane < NT / 32) ? wsum[lane] : 0.f;
#pragma unroll
        for (int off = 4; off > 0; off >>= 1)
            v += __shfl_down_sync(0xffffffffu, v, off);
        if (lane == 0) g_partials[blockIdx.y * CHUNKS + blockIdx.x] = v;
    }
}

__global__ void ssim_final(float* __restrict__ out) {
    __shared__ float buf[512];
    const int t = threadIdx.x;
    buf[t] = (t < NBLK) ? g_partials[t] : 0.f;
    __syncthreads();
#pragma unroll
    for (int s = 256; s > 0; s >>= 1) {
        if (t < s) buf[t] += buf[t + s];
        __syncthreads();
    }
    if (t == 0) {
        constexpr float invN = 1.0f / (float)((size_t)PLANES * W * H);
        out[0] = 1.0f - buf[0] * invN;
    }
}

extern "C" void kernel_launch(void* const* d_in, const int* in_sizes, int n_in,
                              void* d_out, int out_size) {
    const float* X = (const float*)d_in[0];
    const float* Y = (const float*)d_in[1];
    float* out = (float*)d_out;

    dim3 grid(CHUNKS, PLANES);      // 8 x 48 = 384 blocks, 256 threads each
    ssim_main<<<grid, NT>>>(X, Y);
    ssim_final<<<1, 512>>>(out);
}

// round 5
// speedup vs baseline: 1.5748x; 1.0596x over previous
#include <cuda_runtime.h>

namespace {
constexpr int W      = 512;
constexpr int H      = 512;
constexpr int PLANES = 16 * 3;         // 48
constexpr int NBLK   = 296;            // 148 SMs x occ 2, exactly one wave
constexpr int NT     = 256;
constexpr int RB     = 528;            // row buffer floats (stride mult of 16B)
constexpr int MAXRI  = 96;             // max riter = 86 + 10
constexpr float C1c  = 1e-4f;
constexpr float C2c  = 9e-4f;
}

__device__ float g_partials[NBLK];
__device__ int   g_count = 0;

// ---------------- packed f32x2 helpers (sm_103a) ----------------
using u64 = unsigned long long;

static __device__ __forceinline__ u64 pk2(float lo, float hi) {
    u64 r; asm("mov.b64 %0, {%1, %2};" : "=l"(r) : "f"(lo), "f"(hi)); return r;
}
static __device__ __forceinline__ u64 pkf2(float2 v) { return pk2(v.x, v.y); }
static __device__ __forceinline__ void upk2(u64 v, float& lo, float& hi) {
    asm("mov.b64 {%0, %1}, %2;" : "=f"(lo), "=f"(hi) : "l"(v));
}
static __device__ __forceinline__ u64 fma2(u64 a, u64 b, u64 c) {
    u64 d; asm("fma.rn.f32x2 %0, %1, %2, %3;" : "=l"(d) : "l"(a), "l"(b), "l"(c)); return d;
}
static __device__ __forceinline__ u64 add2(u64 a, u64 b) {
    u64 d; asm("add.rn.f32x2 %0, %1, %2;" : "=l"(d) : "l"(a), "l"(b)); return d;
}
static __device__ __forceinline__ u64 mul2(u64 a, u64 b) {
    u64 d; asm("mul.rn.f32x2 %0, %1, %2;" : "=l"(d) : "l"(a), "l"(b)); return d;
}
// (a.hi, b.lo) as a packed pair
static __device__ __forceinline__ u64 hilo(u64 a, u64 b) {
    float al, ah, bl, bh; upk2(a, al, ah); upk2(b, bl, bh); return pk2(ah, bl);
}

// Vertical 11-tap blur of x, y, xx, yy, xy from the register ring.
static __device__ __forceinline__ void vert(const u64 xr[11], const u64 yr[11],
                                            int kk, const u64 Wv[6], u64 v[5]) {
    const int sC = (kk + 6) % 11;
    const u64 xc = xr[sC], yc = yr[sC];
    v[0] = mul2(Wv[5], xc);
    v[1] = mul2(Wv[5], yc);
    v[2] = mul2(Wv[5], mul2(xc, xc));
    v[3] = mul2(Wv[5], mul2(yc, yc));
    v[4] = mul2(Wv[5], mul2(xc, yc));
#pragma unroll
    for (int j = 0; j < 5; ++j) {
        const int sA = (kk + 1 + j) % 11;    // row offset j
        const int sB = (kk + 11 - j) % 11;   // row offset 10-j
        const u64 xa = xr[sA], xb = xr[sB];
        const u64 ya = yr[sA], yb = yr[sB];
        v[0] = fma2(Wv[j], add2(xa, xb), v[0]);
        v[1] = fma2(Wv[j], add2(ya, yb), v[1]);
        v[2] = fma2(Wv[j], fma2(xa, xa, mul2(xb, xb)), v[2]);
        v[3] = fma2(Wv[j], fma2(ya, ya, mul2(yb, yb)), v[3]);
        v[4] = fma2(Wv[j], fma2(xa, ya, mul2(xb, yb)), v[4]);
    }
}

static __device__ __forceinline__ float ssim2(const u64 h[5], u64 C1_2, u64 C2_2,
                                              u64 EPS2, u64 NEG1) {
    const u64 mxx = mul2(h[0], h[0]);
    const u64 myy = mul2(h[1], h[1]);
    const u64 mxy = mul2(h[0], h[1]);
    const u64 sxx = fma2(mxx, NEG1, h[2]);
    const u64 syy = fma2(myy, NEG1, h[3]);
    const u64 sxy = fma2(mxy, NEG1, h[4]);
    const u64 num = mul2(add2(add2(mxy, mxy), C1_2), add2(add2(sxy, sxy), C2_2));
    const u64 den = add2(mul2(add2(add2(mxx, myy), C1_2),
                              add2(add2(sxx, syy), C2_2)), EPS2);
    float n0, n1, d0, d1;
    upk2(num, n0, n1);
    upk2(den, d0, d1);
    return __fdividef(n0, d0) + __fdividef(n1, d1);
}

__global__ __launch_bounds__(NT, 2)
void ssim_main(const float* __restrict__ X, const float* __restrict__ Y,
               float* __restrict__ out) {
    // Double-buffered 2-row exchange: [phase-buffer][row-in-phase][quantity][RB]
    // Data for col c at index 6+c; pads [0..5] and [518..527] stay zero.
    __shared__ __align__(16) float sq[2][2][5][RB];
    __shared__ float wsum[NT / 32];
    __shared__ int amLast;

    const int t = threadIdx.x;              // vertical role: cols (2t, 2t+1)
    const int b = blockIdx.x;               // 0..295

    // ---- Balanced tiling: planes 0-7 have 7 chunks, planes 8-47 have 6 ----
    int plane, r0, ch;
    if (b < 56) {
        plane = b / 7;
        const int c = b % 7;                 // sizes 74,74,74,74,72,72,72
        ch = (c < 4) ? 74 : 72;
        r0 = (c < 4) ? 74 * c : 296 + 72 * (c - 4);
    } else {
        const int bb = b - 56;
        plane = 8 + bb / 6;
        const int c = bb % 6;                // sizes 86,86,86,86,84,84
        ch = (c < 4) ? 86 : 84;
        r0 = (c < 4) ? 86 * c : 344 + 84 * (c - 4);
    }
    const int riter = ch + 10;

    const int hrow = t >> 7;                // horizontal role: row-in-phase
    const int u    = t & 127;               // horizontal role: cols 4u..4u+3

    const float2* __restrict__ X2 =
        reinterpret_cast<const float2*>(X + (size_t)plane * W * H);
    const float2* __restrict__ Y2 =
        reinterpret_cast<const float2*>(Y + (size_t)plane * W * H);

    // Zero pads once (stores below only touch idx [6 .. 517]).
    if (t < 6) {
#pragma unroll
        for (int pb = 0; pb < 2; ++pb)
#pragma unroll
            for (int r = 0; r < 2; ++r)
#pragma unroll
                for (int q = 0; q < 5; ++q) sq[pb][r][q][t] = 0.f;
    }
    if (t < 10) {
#pragma unroll
        for (int pb = 0; pb < 2; ++pb)
#pragma unroll
            for (int r = 0; r < 2; ++r)
#pragma unroll
                for (int q = 0; q < 5; ++q) sq[pb][r][q][518 + t] = 0.f;
    }

    const float Gw[6] = {0.00102838f, 0.00759875f, 0.03600077f,
                         0.10936070f, 0.21300554f, 0.26601172f};
    u64 Wv[6];
#pragma unroll
    for (int i = 0; i < 6; ++i) Wv[i] = pk2(Gw[i], Gw[i]);
    const u64 NEG1 = pk2(-1.f, -1.f);
    const u64 C1_2 = pk2(C1c, C1c);
    const u64 C2_2 = pk2(C2c, C2c);
    const u64 EPS2 = pk2(1e-8f, 1e-8f);

    // Register ring: 11 rows of raw x,y (packed column pair).
    u64 xr[11], yr[11];

    // Prefetch rows 0,1 (image rows r0-5, r0-4).
    float2 p0x, p0y, p1x, p1y;
    {
        const int ra = r0 - 5, rb = r0 - 4;
        const bool oa = ((unsigned)ra < (unsigned)H);
        const bool ob = ((unsigned)rb < (unsigned)H);
        p0x = oa ? X2[(size_t)ra * (W / 2) + t] : make_float2(0.f, 0.f);
        p0y = oa ? Y2[(size_t)ra * (W / 2) + t] : make_float2(0.f, 0.f);
        p1x = ob ? X2[(size_t)rb * (W / 2) + t] : make_float2(0.f, 0.f);
        p1y = ob ? Y2[(size_t)rb * (W / 2) + t] : make_float2(0.f, 0.f);
    }

    float acc = 0.f;

#pragma unroll 1
    for (int outer = 0; outer < MAXRI; outer += 22) {
#pragma unroll
        for (int ph = 0; ph < 11; ++ph) {
            const int rr = outer + 2 * ph;          // even; rows rr, rr+1
            if (rr < riter) {
                const int k0 = (2 * ph) % 11;       // compile-time slots
                const int k1 = (2 * ph + 1) % 11;
                xr[k0] = pkf2(p0x); yr[k0] = pkf2(p0y);
                xr[k1] = pkf2(p1x); yr[k1] = pkf2(p1y);

                // Prefetch rows rr+2, rr+3 (hidden under this phase's compute).
                {
                    const int ra = r0 - 5 + rr + 2, rb = ra + 1;
                    const bool oa = (rr + 2 < riter) && ((unsigned)ra < (unsigned)H);
                    const bool ob = (rr + 3 < riter) && ((unsigned)rb < (unsigned)H);
                    p0x = oa ? X2[(size_t)ra * (W / 2) + t] : make_float2(0.f, 0.f);
                    p0y = oa ? Y2[(size_t)ra * (W / 2) + t] : make_float2(0.f, 0.f);
                    p1x = ob ? X2[(size_t)rb * (W / 2) + t] : make_float2(0.f, 0.f);
                    p1y = ob ? Y2[(size_t)rb * (W / 2) + t] : make_float2(0.f, 0.f);
                }

                if (rr >= 10) {
                    const int pb = (rr >> 1) & 1;   // phase buffer

                    // ---- Vertical blur for output rows rr-10, rr-9 ----
                    u64 v0[5], v1[5];
                    vert(xr, yr, k0, Wv, v0);
                    vert(xr, yr, k1, Wv, v1);

                    // ---- Exchange: aligned STS.64 (idx 6+2t is even) ----
#pragma unroll
                    for (int q = 0; q < 5; ++q) {
                        *reinterpret_cast<u64*>(&sq[pb][0][q][6 + 2 * t]) = v0[q];
                        *reinterpret_cast<u64*>(&sq[pb][1][q][6 + 2 * t]) = v1[q];
                    }
                    __syncthreads();     // one barrier per 2-row phase

                    // ---- Horizontal: 4 cols of one row per thread ----
                    u64 hA[5], hB[5];    // pairs m=0 (cols 4u,4u+1), m=1
#pragma unroll
                    for (int q = 0; q < 5; ++q) {
                        const float4* P =
                            reinterpret_cast<const float4*>(&sq[pb][hrow][q][4 * u]);
                        const float4 a = P[0], bq = P[1], cq = P[2], d = P[3];
                        // U_j = cols (4u-6+2j, 4u-5+2j), j=0..7
                        const u64 U0 = pk2(a.x, a.y),  U1 = pk2(a.z, a.w);
                        const u64 U2 = pk2(bq.x, bq.y), U3 = pk2(bq.z, bq.w);
                        const u64 U4 = pk2(cq.x, cq.y), U5 = pk2(cq.z, cq.w);
                        const u64 U6 = pk2(d.x, d.y),  U7 = pk2(d.z, d.w);
                        const u64 A2 = add2(U2, U3), A3 = add2(U3, U4), A4 = add2(U4, U5);
                        const u64 B1 = add2(U1, U4), B2 = add2(U2, U5), B3 = add2(U3, U6);
                        const u64 Cg0 = add2(U0, U5), Cg1 = add2(U1, U6), Cg2 = add2(U2, U7);
                        // m = 0
                        u64 h = mul2(Wv[5], U3);
                        h = fma2(Wv[3], add2(U2, U4), h);
                        h = fma2(Wv[1], add2(U1, U5), h);
                        h = fma2(Wv[4], hilo(A2, A3), h);
                        h = fma2(Wv[2], hilo(B1, B2), h);
                        h = fma2(Wv[0], hilo(Cg0, Cg1), h);
                        hA[q] = h;
                        // m = 1
                        u64 g = mul2(Wv[5], U4);
                        g = fma2(Wv[3], add2(U3, U5), g);
                        g = fma2(Wv[1], add2(U2, U6), g);
                        g = fma2(Wv[4], hilo(A3, A4), g);
                        g = fma2(Wv[2], hilo(B2, B3), g);
                        g = fma2(Wv[0], hilo(Cg1, Cg2), g);
                        hB[q] = g;
                    }

                    acc += ssim2(hA, C1_2, C2_2, EPS2, NEG1);
                    acc += ssim2(hB, C1_2, C2_2, EPS2, NEG1);
                    // No second barrier: double-buffered across phases.
                }
            }
        }
    }

    // ---- Deterministic block reduction ----
#pragma unroll
    for (int off = 16; off > 0; off >>= 1)
        acc += __shfl_down_sync(0xffffffffu, acc, off);
    const int lane = t & 31, wid = t >> 5;
    if (lane == 0) wsum[wid] = acc;
    __syncthreads();
    if (wid == 0) {
        float v = (lane < NT / 32) ? wsum[lane] : 0.f;
#pragma unroll
        for (int off = 4; off > 0; off >>= 1)
            v += __shfl_down_sync(0xffffffffu, v, off);
        if (lane == 0) g_partials[b] = v;
    }

    // ---- Fused finalize: last block reduces all partials ----
    if (t == 0) {
        __threadfence();
        const int prev = atomicAdd(&g_count, 1);
        amLast = (prev == NBLK - 1);
    }
    __syncthreads();
    if (amLast) {
        float s = (t < NBLK) ? g_partials[t] : 0.f;
        if (t + 256 < NBLK) s += g_partials[t + 256];
#pragma unroll
        for (int off = 16; off > 0; off >>= 1)
            s += __shfl_down_sync(0xffffffffu, s, off);
        if (lane == 0) wsum[wid] = s;
        __syncthreads();
        if (wid == 0) {
            float v = (lane < NT / 32) ? wsum[lane] : 0.f;
#pragma unroll
            for (int off = 4; off > 0; off >>= 1)
                v += __shfl_down_sync(0xffffffffu, v, off);
            if (lane == 0) {
                constexpr float invN = 1.0f / (float)((size_t)PLANES * W * H);
                out[0] = 1.0f - v * invN;
                g_count = 0;        // reset for next graph replay
            }
        }
    }
}

extern "C" void kernel_launch(void* const* d_in, const int* in_sizes, int n_in,
                              void* d_out, int out_size) {
    const float* X = (const float*)d_in[0];
    const float* Y = (const float*)d_in[1];
    float* out = (float*)d_out;

    ssim_main<<<NBLK, NT>>>(X, Y, out);   // 296 blocks = 148 SMs x occ 2
}

// round 6
// speedup vs baseline: 1.8124x; 1.1509x over previous
#include <cuda_runtime.h>

namespace {
constexpr int W      = 512;
constexpr int H      = 512;
constexpr int PLANES = 16 * 3;         // 48
constexpr int NBLK   = 296;            // 148 SMs x occ 2, exactly one wave
constexpr int NT     = 256;
constexpr int RB     = 528;            // row buffer floats (stride mult of 16B)
constexpr int MAXRI  = 96;             // max riter = 86 + 10
constexpr float C1c  = 1e-4f;
constexpr float C2c  = 9e-4f;
}

__device__ float g_partials[NBLK];
__device__ int   g_count = 0;

// ---------------- packed f32x2 helpers (sm_103a) ----------------
using u64 = unsigned long long;

static __device__ __forceinline__ u64 pk2(float lo, float hi) {
    u64 r; asm("mov.b64 %0, {%1, %2};" : "=l"(r) : "f"(lo), "f"(hi)); return r;
}
static __device__ __forceinline__ u64 pkf2(float2 v) { return pk2(v.x, v.y); }
static __device__ __forceinline__ void upk2(u64 v, float& lo, float& hi) {
    asm("mov.b64 {%0, %1}, %2;" : "=f"(lo), "=f"(hi) : "l"(v));
}
static __device__ __forceinline__ u64 fma2(u64 a, u64 b, u64 c) {
    u64 d; asm("fma.rn.f32x2 %0, %1, %2, %3;" : "=l"(d) : "l"(a), "l"(b), "l"(c)); return d;
}
static __device__ __forceinline__ u64 add2(u64 a, u64 b) {
    u64 d; asm("add.rn.f32x2 %0, %1, %2;" : "=l"(d) : "l"(a), "l"(b)); return d;
}
static __device__ __forceinline__ u64 mul2(u64 a, u64 b) {
    u64 d; asm("mul.rn.f32x2 %0, %1, %2;" : "=l"(d) : "l"(a), "l"(b)); return d;
}
// (a.hi, b.lo) as a packed pair
static __device__ __forceinline__ u64 hilo(u64 a, u64 b) {
    float al, ah, bl, bh; upk2(a, al, ah); upk2(b, bl, bh); return pk2(ah, bl);
}

// Vertical 11-tap blur of x, y, p = x^2+y^2, q = x*y from the register ring.
static __device__ __forceinline__ void vert(const u64 xr[11], const u64 yr[11],
                                            int kk, const u64 Wv[6], u64 v[4]) {
    const int sC = (kk + 6) % 11;
    const u64 xc = xr[sC], yc = yr[sC];
    v[0] = mul2(Wv[5], xc);
    v[1] = mul2(Wv[5], yc);
    v[2] = mul2(Wv[5], fma2(xc, xc, mul2(yc, yc)));
    v[3] = mul2(Wv[5], mul2(xc, yc));
#pragma unroll
    for (int j = 0; j < 5; ++j) {
        const int sA = (kk + 1 + j) % 11;    // row offset j
        const int sB = (kk + 11 - j) % 11;   // row offset 10-j
        const u64 xa = xr[sA], xb = xr[sB];
        const u64 ya = yr[sA], yb = yr[sB];
        v[0] = fma2(Wv[j], add2(xa, xb), v[0]);
        v[1] = fma2(Wv[j], add2(ya, yb), v[1]);
        const u64 pa = fma2(xa, xa, mul2(ya, ya));
        const u64 pb = fma2(xb, xb, mul2(yb, yb));
        v[2] = fma2(Wv[j], add2(pa, pb), v[2]);
        v[3] = fma2(Wv[j], fma2(xa, ya, mul2(xb, yb)), v[3]);
    }
}

// h[0]=mu_x, h[1]=mu_y, h[2]=blur(x^2+y^2), h[3]=blur(xy)
static __device__ __forceinline__ float ssim2(const u64 h[4], u64 C1_2, u64 C2_2,
                                              u64 EPS2, u64 NEG1) {
    const u64 musq = fma2(h[0], h[0], mul2(h[1], h[1]));  // mu_x^2 + mu_y^2
    const u64 mxy  = mul2(h[0], h[1]);
    const u64 ssum = fma2(musq, NEG1, h[2]);              // sigma_x^2 + sigma_y^2
    const u64 sxy  = fma2(mxy,  NEG1, h[3]);
    const u64 num = mul2(add2(add2(mxy, mxy), C1_2), add2(add2(sxy, sxy), C2_2));
    const u64 den = add2(mul2(add2(musq, C1_2), add2(ssum, C2_2)), EPS2);
    float n0, n1, d0, d1;
    upk2(num, n0, n1);
    upk2(den, d0, d1);
    return __fdividef(n0, d0) + __fdividef(n1, d1);
}

__global__ __launch_bounds__(NT, 2)
void ssim_main(const float* __restrict__ X, const float* __restrict__ Y,
               float* __restrict__ out) {
    // Double-buffered 2-row exchange: [phase-buffer][row-in-phase][quantity][RB]
    // Data for col c at index 6+c; pads [0..5] and [518..527] stay zero.
    __shared__ __align__(16) float sq[2][2][4][RB];
    __shared__ float wsum[NT / 32];
    __shared__ int amLast;

    const int t = threadIdx.x;              // vertical role: cols (2t, 2t+1)
    const int b = blockIdx.x;               // 0..295

    // ---- Balanced tiling: planes 0-7 have 7 chunks, planes 8-47 have 6 ----
    int plane, r0, ch;
    if (b < 56) {
        plane = b / 7;
        const int c = b % 7;                 // sizes 74,74,74,74,72,72,72
        ch = (c < 4) ? 74 : 72;
        r0 = (c < 4) ? 74 * c : 296 + 72 * (c - 4);
    } else {
        const int bb = b - 56;
        plane = 8 + bb / 6;
        const int c = bb % 6;                // sizes 86,86,86,86,84,84
        ch = (c < 4) ? 86 : 84;
        r0 = (c < 4) ? 86 * c : 344 + 84 * (c - 4);
    }
    const int riter = ch + 10;

    const int hrow = t >> 7;                // horizontal role: row-in-phase
    const int u    = t & 127;               // horizontal role: cols 4u..4u+3

    const float2* __restrict__ X2 =
        reinterpret_cast<const float2*>(X + (size_t)plane * W * H);
    const float2* __restrict__ Y2 =
        reinterpret_cast<const float2*>(Y + (size_t)plane * W * H);

    // Zero pads once (stores below only touch idx [6 .. 517]).
    if (t < 6) {
#pragma unroll
        for (int pb = 0; pb < 2; ++pb)
#pragma unroll
            for (int r = 0; r < 2; ++r)
#pragma unroll
                for (int q = 0; q < 4; ++q) sq[pb][r][q][t] = 0.f;
    }
    if (t < 10) {
#pragma unroll
        for (int pb = 0; pb < 2; ++pb)
#pragma unroll
            for (int r = 0; r < 2; ++r)
#pragma unroll
                for (int q = 0; q < 4; ++q) sq[pb][r][q][518 + t] = 0.f;
    }

    const float Gw[6] = {0.00102838f, 0.00759875f, 0.03600077f,
                         0.10936070f, 0.21300554f, 0.26601172f};
    u64 Wv[6];
#pragma unroll
    for (int i = 0; i < 6; ++i) Wv[i] = pk2(Gw[i], Gw[i]);
    const u64 NEG1 = pk2(-1.f, -1.f);
    const u64 C1_2 = pk2(C1c, C1c);
    const u64 C2_2 = pk2(C2c, C2c);
    const u64 EPS2 = pk2(1e-8f, 1e-8f);

    // Register ring: 11 rows of raw x,y (packed column pair).
    u64 xr[11], yr[11];

    // Prefetch rows 0,1 (image rows r0-5, r0-4).
    float2 p0x, p0y, p1x, p1y;
    {
        const int ra = r0 - 5, rb = r0 - 4;
        const bool oa = ((unsigned)ra < (unsigned)H);
        const bool ob = ((unsigned)rb < (unsigned)H);
        p0x = oa ? X2[(size_t)ra * (W / 2) + t] : make_float2(0.f, 0.f);
        p0y = oa ? Y2[(size_t)ra * (W / 2) + t] : make_float2(0.f, 0.f);
        p1x = ob ? X2[(size_t)rb * (W / 2) + t] : make_float2(0.f, 0.f);
        p1y = ob ? Y2[(size_t)rb * (W / 2) + t] : make_float2(0.f, 0.f);
    }

    float acc = 0.f;

#pragma unroll 1
    for (int outer = 0; outer < MAXRI; outer += 22) {
#pragma unroll
        for (int ph = 0; ph < 11; ++ph) {
            const int rr = outer + 2 * ph;          // even; rows rr, rr+1
            if (rr < riter) {
                const int k0 = (2 * ph) % 11;       // compile-time slots
                const int k1 = (2 * ph + 1) % 11;
                xr[k0] = pkf2(p0x); yr[k0] = pkf2(p0y);
                xr[k1] = pkf2(p1x); yr[k1] = pkf2(p1y);

                // Prefetch rows rr+2, rr+3 (hidden under this phase's compute).
                {
                    const int ra = r0 - 5 + rr + 2, rb = ra + 1;
                    const bool oa = (rr + 2 < riter) && ((unsigned)ra < (unsigned)H);
                    const bool ob = (rr + 3 < riter) && ((unsigned)rb < (unsigned)H);
                    p0x = oa ? X2[(size_t)ra * (W / 2) + t] : make_float2(0.f, 0.f);
                    p0y = oa ? Y2[(size_t)ra * (W / 2) + t] : make_float2(0.f, 0.f);
                    p1x = ob ? X2[(size_t)rb * (W / 2) + t] : make_float2(0.f, 0.f);
                    p1y = ob ? Y2[(size_t)rb * (W / 2) + t] : make_float2(0.f, 0.f);
                }

                if (rr >= 10) {
                    const int pb = (rr >> 1) & 1;   // phase buffer

                    // ---- Vertical blur for output rows rr-10, rr-9 ----
                    u64 v0[4], v1[4];
                    vert(xr, yr, k0, Wv, v0);
                    vert(xr, yr, k1, Wv, v1);

                    // ---- Exchange: aligned STS.64 (idx 6+2t is even) ----
#pragma unroll
                    for (int q = 0; q < 4; ++q) {
                        *reinterpret_cast<u64*>(&sq[pb][0][q][6 + 2 * t]) = v0[q];
                        *reinterpret_cast<u64*>(&sq[pb][1][q][6 + 2 * t]) = v1[q];
                    }
                    __syncthreads();     // one barrier per 2-row phase

                    // ---- Horizontal: 4 cols of one row per thread ----
                    u64 hA[4], hB[4];    // pairs m=0 (cols 4u,4u+1), m=1
#pragma unroll
                    for (int q = 0; q < 4; ++q) {
                        const float4* P =
                            reinterpret_cast<const float4*>(&sq[pb][hrow][q][4 * u]);
                        const float4 a = P[0], bq = P[1], cq = P[2], d = P[3];
                        // U_j = cols (4u-6+2j, 4u-5+2j), j=0..7
                        const u64 U0 = pk2(a.x, a.y),  U1 = pk2(a.z, a.w);
                        const u64 U2 = pk2(bq.x, bq.y), U3 = pk2(bq.z, bq.w);
                        const u64 U4 = pk2(cq.x, cq.y), U5 = pk2(cq.z, cq.w);
                        const u64 U6 = pk2(d.x, d.y),  U7 = pk2(d.z, d.w);
                        const u64 A2 = add2(U2, U3), A3 = add2(U3, U4), A4 = add2(U4, U5);
                        const u64 B1 = add2(U1, U4), B2 = add2(U2, U5), B3 = add2(U3, U6);
                        const u64 Cg0 = add2(U0, U5), Cg1 = add2(U1, U6), Cg2 = add2(U2, U7);
                        // m = 0
                        u64 h = mul2(Wv[5], U3);
                        h = fma2(Wv[3], add2(U2, U4), h);
                        h = fma2(Wv[1], add2(U1, U5), h);
                        h = fma2(Wv[4], hilo(A2, A3), h);
                        h = fma2(Wv[2], hilo(B1, B2), h);
                        h = fma2(Wv[0], hilo(Cg0, Cg1), h);
                        hA[q] = h;
                        // m = 1
                        u64 g = mul2(Wv[5], U4);
                        g = fma2(Wv[3], add2(U3, U5), g);
                        g = fma2(Wv[1], add2(U2, U6), g);
                        g = fma2(Wv[4], hilo(A3, A4), g);
                        g = fma2(Wv[2], hilo(B2, B3), g);
                        g = fma2(Wv[0], hilo(Cg1, Cg2), g);
                        hB[q] = g;
                    }

                    acc += ssim2(hA, C1_2, C2_2, EPS2, NEG1);
                    acc += ssim2(hB, C1_2, C2_2, EPS2, NEG1);
                    // No second barrier: double-buffered across phases.
                }
            }
        }
    }

    // ---- Deterministic block reduction ----
#pragma unroll
    for (int off = 16; off > 0; off >>= 1)
        acc += __shfl_down_sync(0xffffffffu, acc, off);
    const int lane = t & 31, wid = t >> 5;
    if (lane == 0) wsum[wid] = acc;
    __syncthreads();
    if (wid == 0) {
        float v = (lane < NT / 32) ? wsum[lane] : 0.f;
#pragma unroll
        for (int off = 4; off > 0; off >>= 1)
            v += __shfl_down_sync(0xffffffffu, v, off);
        if (lane == 0) g_partials[b] = v;
    }

    // ---- Fused finalize: last block reduces all partials ----
    if (t == 0) {
        __threadfence();
        const int prev = atomicAdd(&g_count, 1);
        amLast = (prev == NBLK - 1);
    }
    __syncthreads();
    if (amLast) {
        float s = (t < NBLK) ? g_partials[t] : 0.f;
        if (t + 256 < NBLK) s += g_partials[t + 256];
#pragma unroll
        for (int off = 16; off > 0; off >>= 1)
            s += __shfl_down_sync(0xffffffffu, s, off);
        if (lane == 0) wsum[wid] = s;
        __syncthreads();
        if (wid == 0) {
            float v = (lane < NT / 32) ? wsum[lane] : 0.f;
#pragma unroll
            for (int off = 4; off > 0; off >>= 1)
                v += __shfl_down_sync(0xffffffffu, v, off);
            if (lane == 0) {
                constexpr float invN = 1.0f / (float)((size_t)PLANES * W * H);
                out[0] = 1.0f - v * invN;
                g_count = 0;        // reset for next graph replay
            }
        }
    }
}

extern "C" void kernel_launch(void* const* d_in, const int* in_sizes, int n_in,
                              void* d_out, int out_size) {
    const float* X = (const float*)d_in[0];
    const float* Y = (const float*)d_in[1];
    float* out = (float*)d_out;

    ssim_main<<<NBLK, NT>>>(X, Y, out);   // 296 blocks = 148 SMs x occ 2
}